// round 13
// baseline (speedup 1.0000x reference)
#include <cuda_runtime.h>
#include <cuda_fp16.h>
#include <cstdint>

// 4D conv (VALID, stride 1) + ReLU via mma.sync m16n8k16 fp16 (fp32 accum).
// Occupancy experiment: 3 CTAs/SM (warp = 2 rows x 16 px, acc 32 regs).
// in  : [2,16,8,8,64,64] f32 -> g_xh[b,d1,d2,y,x][c16perm] fp16 (padded tail)
// wgt : [32,16,3,3,3,3]  f32 -> g_wh[ij9][kl9][oc32][c16perm] fp16
// out : [2,32,6,6,62,62] f32
//
// CTA = (16x16 px tile, b*z1*z2), 256 thr = 8 warps; warp = 2 rows x 16 px x
// 32 oc. TMA bulk staging, triple buffer, 9 ij stages. Pre-kernels merged.

typedef unsigned int u32;

__device__ __half g_xh[2 * 8 * 8 * 64 * 64 * 16 + 8192];   // pad
__device__ __half g_wh[9 * 9 * 32 * 16];

// ---------------- merged pre-kernel ----------------

__global__ void pre_kernel(const float* __restrict__ x,
                           const float* __restrict__ wgt) {
    const int bid = blockIdx.x;
    if (bid < 1024) {
        const int id = bid * 256 + threadIdx.x;    // 262144 (2 px each)
        const int xp = id & 31;
        const int y  = (id >> 5) & 63;
        const int d2 = (id >> 11) & 7;
        const int d1 = (id >> 14) & 7;
        const int b  = id >> 17;
        const long sp = ((((long)b * 16) * 8 + d1) * 8 + d2) * 4096 + y * 64 + xp * 2;
        float2 v[16];
#pragma unroll
        for (int c = 0; c < 16; c++)
            v[c] = *(const float2*)(x + sp + (long)c * 262144);
        const long dbase = ((((long)(b * 8 + d1) * 8 + d2) * 64 + y) * 64 + xp * 2) * 16;
#pragma unroll
        for (int pos = 0; pos < 2; pos++) {
            __half2 h[8];
#pragma unroll
            for (int t = 0; t < 4; t++) {
                h[2 * t]     = __floats2half2_rn(pos ? v[2 * t].y     : v[2 * t].x,
                                                 pos ? v[2 * t + 1].y : v[2 * t + 1].x);
                h[2 * t + 1] = __floats2half2_rn(pos ? v[2 * t + 8].y : v[2 * t + 8].x,
                                                 pos ? v[2 * t + 9].y : v[2 * t + 9].x);
            }
            uint4* dst = reinterpret_cast<uint4*>(g_xh + dbase + pos * 16);
            const u32* hu = reinterpret_cast<const u32*>(h);
            dst[0] = make_uint4(hu[0], hu[1], hu[2], hu[3]);
            dst[1] = make_uint4(hu[4], hu[5], hu[6], hu[7]);
        }
    } else {
        const int id = (bid - 1024) * 256 + threadIdx.x;
        if (id < 9 * 9 * 32 * 16) {
            const int p  = id & 15;
            const int oc = (id >> 4) & 31;
            const int kl = (id >> 9) % 9;
            const int ij = (id >> 9) / 9;
            const int t  = p >> 2, u = p & 3;
            const int ch = (u < 2) ? (2 * t + u) : (2 * t + 6 + u);   // perm
            const float v = wgt[oc * 1296 + ch * 81 + (ij / 3) * 27 + (ij % 3) * 9
                                + (kl / 3) * 3 + (kl % 3)];
            g_wh[id] = __float2half_rn(v);
        }
    }
}

// ---------------- helpers ----------------

__device__ __forceinline__ void bulk_g2s(u32 dst, const void* src, u32 bytes, u32 mbar) {
    asm volatile(
        "cp.async.bulk.shared::cluster.global.mbarrier::complete_tx::bytes "
        "[%0], [%1], %2, [%3];"
        :: "r"(dst), "l"(src), "r"(bytes), "r"(mbar) : "memory");
}
__device__ __forceinline__ void mbar_init(u32 mbar, u32 cnt) {
    asm volatile("mbarrier.init.shared.b64 [%0], %1;" :: "r"(mbar), "r"(cnt) : "memory");
}
__device__ __forceinline__ void mbar_expect(u32 mbar, u32 bytes) {
    asm volatile("mbarrier.arrive.expect_tx.shared.b64 _, [%0], %1;"
                 :: "r"(mbar), "r"(bytes) : "memory");
}
__device__ __forceinline__ void mbar_wait(u32 mbar, u32 parity) {
    u32 done;
    asm volatile(
        "{\n\t.reg .pred p;\n\t"
        "mbarrier.try_wait.parity.acquire.cta.shared::cta.b64 p, [%1], %2;\n\t"
        "selp.b32 %0, 1, 0, p;\n\t}"
        : "=r"(done) : "r"(mbar), "r"(parity) : "memory");
    if (!done) {
        asm volatile(
            "{\n\t.reg .pred P1;\n\t"
            "WL_%=:\n\t"
            "mbarrier.try_wait.parity.acquire.cta.shared::cta.b64 P1, [%0], %1, 0x989680;\n\t"
            "@P1 bra.uni WD_%=;\n\t"
            "bra.uni WL_%=;\n\t"
            "WD_%=:\n\t}"
            :: "r"(mbar), "r"(parity) : "memory");
    }
}

#define MMA_F16(d, a0, a1, a2, a3, b0, b1)                                    \
    asm volatile(                                                             \
        "mma.sync.aligned.m16n8k16.row.col.f32.f16.f16.f32 "                  \
        "{%0,%1,%2,%3}, {%4,%5,%6,%7}, {%8,%9}, {%0,%1,%2,%3};"               \
        : "+f"((d)[0]), "+f"((d)[1]), "+f"((d)[2]), "+f"((d)[3])              \
        : "r"(a0), "r"(a1), "r"(a2), "r"(a3), "r"(b0), "r"(b1))

#define SXH 5184          // 18 rows * 18 pos * 16 halves
#define SWH 4608          // 9 taps * 32 oc * 16 halves
#define BUFH (SXH + SWH)  // 9792 halves = 19584 B
#define STAGE_BYTES 19584u
#define SMEM_BYTES (3 * BUFH * 2)   // 58752 (epilogue xpose needs 36864 -- fits)

// ---------------- main kernel ----------------

__global__ __launch_bounds__(256, 3)
void conv4d_f16_mma3_kernel(float* __restrict__ out)
{
    extern __shared__ __align__(128) __half smh[];
    __shared__ __align__(8) unsigned long long s_mbar[3];

    const u32 su = (u32)__cvta_generic_to_shared(smh);
    const u32 mb = (u32)__cvta_generic_to_shared(s_mbar);

    const int tid  = threadIdx.x;
    const int w    = tid >> 5;          // warp 0..7 -> rows 2w, 2w+1
    const int lane = tid & 31;
    const int lg   = lane >> 2;
    const int tg   = lane & 3;
    const int w2   = 2 * w;

    const int x0 = 16 * blockIdx.x;     // 0..48
    const int y0 = 16 * blockIdx.y;     // 0..48
    const int zb = blockIdx.z;
    const int b  = zb / 36;
    const int zr = zb % 36;
    const int z1 = zr / 6, z2 = zr % 6;

    if (tid == 0) {
        mbar_init(mb,      1u);
        mbar_init(mb + 8,  1u);
        mbar_init(mb + 16, 1u);
    }
    __syncthreads();

#define ISSUE(K) do {                                                         \
    const int i_ = (K) / 3, j_ = (K) % 3;                                     \
    const long xgb = (((long)(b * 8 + z1 + i_) * 8 + (z2 + j_)) * 4096) * 16; \
    const u32 bufu = su + (u32)((K) % 3) * (BUFH * 2);                        \
    const u32 m = mb + (u32)((K) % 3) * 8;                                    \
    mbar_expect(m, STAGE_BYTES);                                              \
    const __half* xsrc = g_xh + xgb + ((long)y0 * 64 + x0) * 16;              \
    for (int ry = 0; ry < 18; ry++)                                           \
        bulk_g2s(bufu + ry * 576, xsrc + (long)ry * 1024, 576, m);            \
    bulk_g2s(bufu + SXH * 2, g_wh + (K) * 4608, 9216, m);                     \
} while (0)

    if (tid == 0) { ISSUE(0); ISSUE(1); ISSUE(2); }

    float acc[2][4][4];
#pragma unroll
    for (int mt = 0; mt < 2; mt++)
#pragma unroll
        for (int n = 0; n < 4; n++)
#pragma unroll
            for (int r = 0; r < 4; r++)
                acc[mt][n][r] = 0.f;

    const int poff = lg * 16 + tg * 4;

#pragma unroll 1
    for (int ij = 0; ij < 9; ij++) {
        mbar_wait(mb + (u32)(ij % 3) * 8, (u32)((ij / 3) & 1));

        const __half* __restrict__ sx = smh + (ij % 3) * BUFH;
        const __half* __restrict__ sw = sx + SXH;

#pragma unroll
        for (int kl = 0; kl < 9; kl++) {
            const int kk = kl / 3, ll = kl % 3;
            // A frags: mt = output row (w2+mt), m-dim = 16 px
            const __half* a0p = sx + ((w2 + kk) * 18 + ll) * 16 + poff;
            const uint2 A00 = *(const uint2*)(a0p);          // mt0 (a0,a2)
            const uint2 A01 = *(const uint2*)(a0p + 128);    // mt0 (a1,a3)
            const uint2 A10 = *(const uint2*)(a0p + 288);    // mt1 (row +1)
            const uint2 A11 = *(const uint2*)(a0p + 416);

            const __half* swp = sw + kl * 512 + poff;
            const uint2 B0 = *(const uint2*)(swp);
            const uint2 B1 = *(const uint2*)(swp + 128);
            const uint2 B2 = *(const uint2*)(swp + 256);
            const uint2 B3 = *(const uint2*)(swp + 384);

            MMA_F16(acc[0][0], A00.x, A01.x, A00.y, A01.y, B0.x, B0.y);
            MMA_F16(acc[0][1], A00.x, A01.x, A00.y, A01.y, B1.x, B1.y);
            MMA_F16(acc[0][2], A00.x, A01.x, A00.y, A01.y, B2.x, B2.y);
            MMA_F16(acc[0][3], A00.x, A01.x, A00.y, A01.y, B3.x, B3.y);
            MMA_F16(acc[1][0], A10.x, A11.x, A10.y, A11.y, B0.x, B0.y);
            MMA_F16(acc[1][1], A10.x, A11.x, A10.y, A11.y, B1.x, B1.y);
            MMA_F16(acc[1][2], A10.x, A11.x, A10.y, A11.y, B2.x, B2.y);
            MMA_F16(acc[1][3], A10.x, A11.x, A10.y, A11.y, B3.x, B3.y);
        }

        __syncthreads();                 // all warps done reading buf ij%3
        if (ij + 3 < 9 && tid == 0) ISSUE(ij + 3);
    }

    // ---- epilogue: smem transpose -> coalesced float2 stores
    // st[(y*32 + oc)*18 + px], y 0..15, oc 0..31, px 0..15 (stride 18: even)
    float* st = reinterpret_cast<float*>(smh);
#pragma unroll
    for (int mt = 0; mt < 2; mt++) {
        const int yl = w2 + mt;
#pragma unroll
        for (int n = 0; n < 4; n++) {
            const int ocb = 8 * n + 2 * tg;
            st[(yl * 32 + ocb)     * 18 + lg]     = acc[mt][n][0];
            st[(yl * 32 + ocb + 1) * 18 + lg]     = acc[mt][n][1];
            st[(yl * 32 + ocb)     * 18 + lg + 8] = acc[mt][n][2];
            st[(yl * 32 + ocb + 1) * 18 + lg + 8] = acc[mt][n][3];
        }
    }
    __syncthreads();

    const long ob = (long)b * 4428288 + (z1 * 6 + z2) * 3844;
#pragma unroll
    for (int k = 0; k < 16; k++) {
        const int v  = k * 256 + tid;          // 4096 float2 units
        const int p  = v & 7;                  // 8 float2 per 16-px row
        const int oc = (v >> 3) & 31;
        const int y  = v >> 8;
        const int gy = y0 + y;
        const int px = x0 + 2 * p;
        if (gy < 62 && px < 62) {
            float2 val = *(const float2*)(st + (y * 32 + oc) * 18 + 2 * p);
            val.x = fmaxf(val.x, 0.f);
            val.y = fmaxf(val.y, 0.f);
            *(float2*)(out + ob + (long)oc * 138384 + (long)gy * 62 + px) = val;
        }
    }
}

extern "C" void kernel_launch(void* const* d_in, const int* in_sizes, int n_in,
                              void* d_out, int out_size)
{
    const float* x   = (const float*)d_in[0];
    const float* wgt = (const float*)d_in[1];
    float* out = (float*)d_out;

    cudaFuncSetAttribute(conv4d_f16_mma3_kernel,
                         cudaFuncAttributeMaxDynamicSharedMemorySize, SMEM_BYTES);

    pre_kernel<<<1186, 256>>>(x, wgt);
    conv4d_f16_mma3_kernel<<<dim3(4, 4, 72), 256, SMEM_BYTES>>>(out);
}

// round 14
// speedup vs baseline: 1.0457x; 1.0457x over previous
#include <cuda_runtime.h>
#include <cuda_fp16.h>
#include <cstdint>

// 4D conv (VALID, stride 1) + ReLU via mma.sync m16n8k16 fp16 (fp32 accum).
// Fat warp tile: warp = M=128 (4 rows x 32 px) x N=32 oc; 4 warps/CTA.
// 0.375 LDS.64 per MMA, 32-MMA independent bursts per tap.
// in  : [2,16,8,8,64,64] f32 -> g_xh[b,d1,d2,y,x][c16perm] fp16 (padded tail)
// wgt : [32,16,3,3,3,3]  f32 -> g_wh[ij9][kl9][oc32][c16perm] fp16
// out : [2,32,6,6,62,62] f32

typedef unsigned int u32;

__device__ __half g_xh[2 * 8 * 8 * 64 * 64 * 16 + 8192];
__device__ __half g_wh[9 * 9 * 32 * 16];

// ---------------- merged pre-kernel ----------------

__global__ void pre_kernel(const float* __restrict__ x,
                           const float* __restrict__ wgt) {
    const int bid = blockIdx.x;
    if (bid < 1024) {
        const int id = bid * 256 + threadIdx.x;    // 262144 (2 px each)
        const int xp = id & 31;
        const int y  = (id >> 5) & 63;
        const int d2 = (id >> 11) & 7;
        const int d1 = (id >> 14) & 7;
        const int b  = id >> 17;
        const long sp = ((((long)b * 16) * 8 + d1) * 8 + d2) * 4096 + y * 64 + xp * 2;
        float2 v[16];
#pragma unroll
        for (int c = 0; c < 16; c++)
            v[c] = *(const float2*)(x + sp + (long)c * 262144);
        const long dbase = ((((long)(b * 8 + d1) * 8 + d2) * 64 + y) * 64 + xp * 2) * 16;
#pragma unroll
        for (int pos = 0; pos < 2; pos++) {
            __half2 h[8];
#pragma unroll
            for (int t = 0; t < 4; t++) {
                h[2 * t]     = __floats2half2_rn(pos ? v[2 * t].y     : v[2 * t].x,
                                                 pos ? v[2 * t + 1].y : v[2 * t + 1].x);
                h[2 * t + 1] = __floats2half2_rn(pos ? v[2 * t + 8].y : v[2 * t + 8].x,
                                                 pos ? v[2 * t + 9].y : v[2 * t + 9].x);
            }
            uint4* dst = reinterpret_cast<uint4*>(g_xh + dbase + pos * 16);
            const u32* hu = reinterpret_cast<const u32*>(h);
            dst[0] = make_uint4(hu[0], hu[1], hu[2], hu[3]);
            dst[1] = make_uint4(hu[4], hu[5], hu[6], hu[7]);
        }
    } else {
        const int id = (bid - 1024) * 256 + threadIdx.x;
        if (id < 9 * 9 * 32 * 16) {
            const int p  = id & 15;
            const int oc = (id >> 4) & 31;
            const int kl = (id >> 9) % 9;
            const int ij = (id >> 9) / 9;
            const int t  = p >> 2, u = p & 3;
            const int ch = (u < 2) ? (2 * t + u) : (2 * t + 6 + u);
            const float v = wgt[oc * 1296 + ch * 81 + (ij / 3) * 27 + (ij % 3) * 9
                                + (kl / 3) * 3 + (kl % 3)];
            g_wh[id] = __float2half_rn(v);
        }
    }
}

// ---------------- helpers ----------------

__device__ __forceinline__ void bulk_g2s(u32 dst, const void* src, u32 bytes, u32 mbar) {
    asm volatile(
        "cp.async.bulk.shared::cluster.global.mbarrier::complete_tx::bytes "
        "[%0], [%1], %2, [%3];"
        :: "r"(dst), "l"(src), "r"(bytes), "r"(mbar) : "memory");
}
__device__ __forceinline__ void mbar_init(u32 mbar, u32 cnt) {
    asm volatile("mbarrier.init.shared.b64 [%0], %1;" :: "r"(mbar), "r"(cnt) : "memory");
}
__device__ __forceinline__ void mbar_expect(u32 mbar, u32 bytes) {
    asm volatile("mbarrier.arrive.expect_tx.shared.b64 _, [%0], %1;"
                 :: "r"(mbar), "r"(bytes) : "memory");
}
__device__ __forceinline__ void mbar_wait(u32 mbar, u32 parity) {
    u32 done;
    asm volatile(
        "{\n\t.reg .pred p;\n\t"
        "mbarrier.try_wait.parity.acquire.cta.shared::cta.b64 p, [%1], %2;\n\t"
        "selp.b32 %0, 1, 0, p;\n\t}"
        : "=r"(done) : "r"(mbar), "r"(parity) : "memory");
    if (!done) {
        asm volatile(
            "{\n\t.reg .pred P1;\n\t"
            "WL_%=:\n\t"
            "mbarrier.try_wait.parity.acquire.cta.shared::cta.b64 P1, [%0], %1, 0x989680;\n\t"
            "@P1 bra.uni WD_%=;\n\t"
            "bra.uni WL_%=;\n\t"
            "WD_%=:\n\t}"
            :: "r"(mbar), "r"(parity) : "memory");
    }
}

#define MMA_F16(d, a0, a1, a2, a3, b0, b1)                                    \
    asm volatile(                                                             \
        "mma.sync.aligned.m16n8k16.row.col.f32.f16.f16.f32 "                  \
        "{%0,%1,%2,%3}, {%4,%5,%6,%7}, {%8,%9}, {%0,%1,%2,%3};"               \
        : "+f"((d)[0]), "+f"((d)[1]), "+f"((d)[2]), "+f"((d)[3])              \
        : "r"(a0), "r"(a1), "r"(a2), "r"(a3), "r"(b0), "r"(b1))

#define SXH 9792          // 18 rows * 34 pos * 16 halves
#define SWH 4608          // 9 taps * 32 oc * 16 halves
#define BUFH (SXH + SWH)  // 14400 halves = 28800 B
#define STAGE_BYTES 28800u
#define SMEM_BYTES (3 * BUFH * 2)   // 86400 (epilogue xpose needs 69632 -- fits)

// ---------------- main kernel ----------------

__global__ __launch_bounds__(128, 2)
void conv4d_f16_m128_kernel(float* __restrict__ out)
{
    extern __shared__ __align__(128) __half smh[];
    __shared__ __align__(8) unsigned long long s_mbar[3];

    const u32 su = (u32)__cvta_generic_to_shared(smh);
    const u32 mb = (u32)__cvta_generic_to_shared(s_mbar);

    const int tid  = threadIdx.x;
    const int w    = tid >> 5;          // warp 0..3 -> rows 4w..4w+3
    const int lane = tid & 31;
    const int lg   = lane >> 2;
    const int tg   = lane & 3;
    const int w4   = 4 * w;

    const int x0 = 32 * blockIdx.x;     // 0, 32
    const int y0 = 16 * blockIdx.y;     // 0, 16, 32, 48
    const int zb = blockIdx.z;
    const int b  = zb / 36;
    const int zr = zb % 36;
    const int z1 = zr / 6, z2 = zr % 6;

    if (tid == 0) {
        mbar_init(mb,      1u);
        mbar_init(mb + 8,  1u);
        mbar_init(mb + 16, 1u);
    }
    __syncthreads();

#define ISSUE(K) do {                                                         \
    const int i_ = (K) / 3, j_ = (K) % 3;                                     \
    const long xgb = (((long)(b * 8 + z1 + i_) * 8 + (z2 + j_)) * 4096) * 16; \
    const u32 bufu = su + (u32)((K) % 3) * (BUFH * 2);                        \
    const u32 m = mb + (u32)((K) % 3) * 8;                                    \
    mbar_expect(m, STAGE_BYTES);                                              \
    const __half* xsrc = g_xh + xgb + ((long)y0 * 64 + x0) * 16;              \
    for (int ry = 0; ry < 18; ry++)                                           \
        bulk_g2s(bufu + ry * 1088, xsrc + (long)ry * 1024, 1088, m);          \
    bulk_g2s(bufu + SXH * 2, g_wh + (K) * 4608, 9216, m);                     \
} while (0)

    if (tid == 0) { ISSUE(0); ISSUE(1); ISSUE(2); }

    float acc[8][4][4];
#pragma unroll
    for (int m = 0; m < 8; m++)
#pragma unroll
        for (int n = 0; n < 4; n++)
#pragma unroll
            for (int r = 0; r < 4; r++)
                acc[m][n][r] = 0.f;

    const int poff = lg * 16 + tg * 4;

#pragma unroll 1
    for (int ij = 0; ij < 9; ij++) {
        mbar_wait(mb + (u32)(ij % 3) * 8, (u32)((ij / 3) & 1));

        const __half* __restrict__ sx = smh + (ij % 3) * BUFH;
        const __half* __restrict__ sw = sx + SXH;

#pragma unroll
        for (int ll = 0; ll < 3; ll++) {
            // A block: 6 input rows x 2 x-halves x 2 uint2, reused across kk
            uint2 Ar[6][2][2];
#pragma unroll
            for (int r = 0; r < 6; r++) {
                const __half* axp = sx + ((w4 + r) * 34 + ll) * 16 + poff;
                Ar[r][0][0] = *(const uint2*)(axp);
                Ar[r][0][1] = *(const uint2*)(axp + 128);
                Ar[r][1][0] = *(const uint2*)(axp + 256);
                Ar[r][1][1] = *(const uint2*)(axp + 384);
            }
#pragma unroll
            for (int kk = 0; kk < 3; kk++) {
                const __half* swp = sw + (kk * 3 + ll) * 512 + poff;
                const uint2 B0 = *(const uint2*)(swp);
                const uint2 B1 = *(const uint2*)(swp + 128);
                const uint2 B2 = *(const uint2*)(swp + 256);
                const uint2 B3 = *(const uint2*)(swp + 384);
#pragma unroll
                for (int m = 0; m < 8; m++) {
                    const int r  = kk + (m >> 1);
                    const int xh = m & 1;
                    const u32 a0 = Ar[r][xh][0].x, a1 = Ar[r][xh][1].x;
                    const u32 a2 = Ar[r][xh][0].y, a3 = Ar[r][xh][1].y;
                    MMA_F16(acc[m][0], a0, a1, a2, a3, B0.x, B0.y);
                    MMA_F16(acc[m][1], a0, a1, a2, a3, B1.x, B1.y);
                    MMA_F16(acc[m][2], a0, a1, a2, a3, B2.x, B2.y);
                    MMA_F16(acc[m][3], a0, a1, a2, a3, B3.x, B3.y);
                }
            }
        }

        __syncthreads();                 // all warps done reading buf ij%3
        if (ij + 3 < 9 && tid == 0) ISSUE(ij + 3);
    }

    // ---- epilogue: smem transpose (stride 34 -- even) -> coalesced float2
    float* st = reinterpret_cast<float*>(smh);
#pragma unroll
    for (int m = 0; m < 8; m++) {
        const int yl  = w4 + (m >> 1);
        const int pxb = 16 * (m & 1) + lg;
#pragma unroll
        for (int n = 0; n < 4; n++) {
            const int ocb = 8 * n + 2 * tg;
            st[(yl * 32 + ocb)     * 34 + pxb]     = acc[m][n][0];
            st[(yl * 32 + ocb + 1) * 34 + pxb]     = acc[m][n][1];
            st[(yl * 32 + ocb)     * 34 + pxb + 8] = acc[m][n][2];
            st[(yl * 32 + ocb + 1) * 34 + pxb + 8] = acc[m][n][3];
        }
    }
    __syncthreads();

    const long ob = (long)b * 4428288 + (z1 * 6 + z2) * 3844;
#pragma unroll
    for (int k = 0; k < 64; k++) {
        const int v  = k * 128 + tid;          // 8192 float2 units
        const int p  = v & 15;                 // 16 float2 per 32-px row
        const int oc = (v >> 4) & 31;
        const int y  = v >> 9;
        const int gy = y0 + y;
        const int px = x0 + 2 * p;
        if (gy < 62 && px < 62) {
            float2 val = *(const float2*)(st + (y * 32 + oc) * 34 + 2 * p);
            val.x = fmaxf(val.x, 0.f);
            val.y = fmaxf(val.y, 0.f);
            *(float2*)(out + ob + (long)oc * 138384 + (long)gy * 62 + px) = val;
        }
    }
}

extern "C" void kernel_launch(void* const* d_in, const int* in_sizes, int n_in,
                              void* d_out, int out_size)
{
    const float* x   = (const float*)d_in[0];
    const float* wgt = (const float*)d_in[1];
    float* out = (float*)d_out;

    cudaFuncSetAttribute(conv4d_f16_m128_kernel,
                         cudaFuncAttributeMaxDynamicSharedMemorySize, SMEM_BYTES);

    pre_kernel<<<1186, 256>>>(x, wgt);
    conv4d_f16_m128_kernel<<<dim3(2, 4, 72), 128, SMEM_BYTES>>>(out);
}